// round 6
// baseline (speedup 1.0000x reference)
#include <cuda_runtime.h>
#include <cuda_bf16.h>
#include <cstdint>

#define NN 1000
#define FF 64
#define SS 192            // B*T snapshots
#define EMAX 16384
#define KD 576            // 9 slots * 64
#define ROWS (SS*NN)      // 192000
#define NSTAGE 18         // 576/32

// ---------------- scratch (static device memory; no runtime allocs) ----------------
__device__ float g_T[(size_t)ROWS * KD];       // A matrix, row-major [192000][576]
__device__ float g_hn[(size_t)ROWS * FF];      // normalized hidden
__device__ float g_W[KD * 128];                // combined weights [576][128]
__device__ float g_bias[128];
__device__ float g_invdo[NN], g_invdi[NN];
__device__ int   g_ptr_o[NN + 1], g_ptr_i[NN + 1];
__device__ int   g_cur_o[NN], g_cur_i[NN];
__device__ int   g_src_o[EMAX];
__device__ float g_w_o[EMAX];
__device__ int   g_col_i[EMAX];
__device__ float g_part[192 * 40];

// ---------------- fused setup: degrees + scans + csr offsets ----------------
__global__ void k_setup(const int* __restrict__ ei, int E) {
    __shared__ int sdo[NN], sdi[NN];
    __shared__ int sa[1024], sb[1024];
    int t = threadIdx.x;
    if (t < NN) { sdo[t] = 0; sdi[t] = 0; }
    __syncthreads();
    for (int e = t; e < E; e += 1024) {
        atomicAdd(&sdo[ei[e]], 1);
        atomicAdd(&sdi[ei[E + e]], 1);
    }
    __syncthreads();
    // scan deg_in -> ptr_o (CSR bucketed by dst)
    int v = (t < NN) ? sdi[t] : 0;
    sa[t] = v; __syncthreads();
    int* pin = sa; int* pout = sb;
    for (int off = 1; off < 1024; off <<= 1) {
        int x = pin[t]; if (t >= off) x += pin[t - off];
        pout[t] = x; __syncthreads();
        int* tmp = pin; pin = pout; pout = tmp;
    }
    if (t < NN) {
        int incl = pin[t];
        g_ptr_o[t + 1] = incl;
        g_cur_o[t] = incl - sdi[t];
        if (t == 0) g_ptr_o[0] = 0;
        g_invdi[t] = (sdi[t] > 0) ? (1.0f / (float)sdi[t]) : 0.0f;
    }
    __syncthreads();
    // scan deg_out -> ptr_i (CSR bucketed by src)
    v = (t < NN) ? sdo[t] : 0;
    sa[t] = v; __syncthreads();
    pin = sa; pout = sb;
    for (int off = 1; off < 1024; off <<= 1) {
        int x = pin[t]; if (t >= off) x += pin[t - off];
        pout[t] = x; __syncthreads();
        int* tmp = pin; pin = pout; pout = tmp;
    }
    if (t < NN) {
        int incl = pin[t];
        g_ptr_i[t + 1] = incl;
        g_cur_i[t] = incl - sdo[t];
        if (t == 0) g_ptr_i[0] = 0;
        g_invdo[t] = (sdo[t] > 0) ? (1.0f / (float)sdo[t]) : 0.0f;
    }
}

__global__ void k_scatter(const int* __restrict__ ei, int E) {
    int e = blockIdx.x * blockDim.x + threadIdx.x;
    if (e < E) {
        int r = ei[e], c = ei[E + e];
        int p = atomicAdd(&g_cur_o[c], 1);
        g_src_o[p] = r;
        g_w_o[p] = g_invdo[r];
        int q = atomicAdd(&g_cur_i[r], 1);
        g_col_i[q] = c;
    }
}

// combined weight: slot 0 = sum over dir of W[.,0]; slots 1..4 = out-dir k; 5..8 = in-dir k
// cols 0..63 from W_z, 64..127 from W_h; only top F input channels (H-half is zero)
__global__ void k_prepw(const float* __restrict__ Wz, const float* __restrict__ Wh,
                        const float* __restrict__ bz, const float* __restrict__ bh) {
    int kidx = blockIdx.x;        // 0..575
    int n = threadIdx.x;          // 0..127
    int slot = kidx >> 6, c = kidx & 63;
    int j = n & 63;
    const float* Wp = (n < 64) ? Wz : Wh;
    float val;
    if (slot == 0) {
        val = Wp[(size_t)(0 * 128 + c) * 64 + j] + Wp[(size_t)(5 * 128 + c) * 64 + j];
    } else if (slot <= 4) {
        val = Wp[(size_t)(slot * 128 + c) * 64 + j];
    } else {
        val = Wp[(size_t)((5 + (slot - 4)) * 128 + c) * 64 + j];
    }
    g_W[kidx * 128 + n] = val;
    if (kidx == 0) g_bias[n] = (n < 64) ? bz[n] : bh[n - 64];
}

// ---------------- fused Chebyshev chain: one CTA = (snapshot, 4-feature chunk) ----------------
// 4 smem buffers, in-place rotation: per step (t0,o,i,f): newO->f, newI->t0 (safe: t0 is
// only read at own node as the subtraction term), then roles rotate.
__global__ void k_chain(const float* __restrict__ x) {
    extern __shared__ float4 sm4[];
    float4* bufs[4] = { sm4, sm4 + 1024, sm4 + 2048, sm4 + 3072 };
    int s  = blockIdx.x >> 4;
    int fc = blockIdx.x & 15;
    int tid = threadIdx.x;
    const float* xs = x + (size_t)s * NN * 64 + fc * 4;
    float* Tb = g_T + (size_t)s * NN * KD + fc * 4;

    // slot 0 = x
    for (int n = tid; n < NN; n += 256) {
        float4 v = *(const float4*)(xs + (size_t)n * 64);
        bufs[0][n] = v;
        *(float4*)(Tb + (size_t)n * KD) = v;
    }
    __syncthreads();

    // k = 1: O1 = P_o(x) -> buf1, I1 = P_i(x) -> buf2
    for (int n = tid; n < NN; n += 256) {
        float4 ao = make_float4(0.f, 0.f, 0.f, 0.f);
        int p0 = g_ptr_o[n], p1 = g_ptr_o[n + 1];
        for (int p = p0; p < p1; ++p) {
            float w = g_w_o[p];
            float4 v = bufs[0][g_src_o[p]];
            ao.x = fmaf(w, v.x, ao.x); ao.y = fmaf(w, v.y, ao.y);
            ao.z = fmaf(w, v.z, ao.z); ao.w = fmaf(w, v.w, ao.w);
        }
        float4 ai = make_float4(0.f, 0.f, 0.f, 0.f);
        p0 = g_ptr_i[n]; p1 = g_ptr_i[n + 1];
        for (int p = p0; p < p1; ++p) {
            float4 v = bufs[0][g_col_i[p]];
            ai.x += v.x; ai.y += v.y; ai.z += v.z; ai.w += v.w;
        }
        float wi = g_invdi[n];
        ai.x *= wi; ai.y *= wi; ai.z *= wi; ai.w *= wi;
        bufs[1][n] = ao; bufs[2][n] = ai;
        *(float4*)(Tb + (size_t)n * KD + 1 * 64) = ao;
        *(float4*)(Tb + (size_t)n * KD + 5 * 64) = ai;
    }
    __syncthreads();

    // k = 2..4
    float4 *t0 = bufs[0], *bo = bufs[1], *bi = bufs[2], *bf = bufs[3];
    for (int k = 2; k <= 4; ++k) {
        for (int n = tid; n < NN; n += 256) {
            float4 sub = t0[n];
            float4 ao = make_float4(0.f, 0.f, 0.f, 0.f);
            int p0 = g_ptr_o[n], p1 = g_ptr_o[n + 1];
            for (int p = p0; p < p1; ++p) {
                float w = g_w_o[p];
                float4 v = bo[g_src_o[p]];
                ao.x = fmaf(w, v.x, ao.x); ao.y = fmaf(w, v.y, ao.y);
                ao.z = fmaf(w, v.z, ao.z); ao.w = fmaf(w, v.w, ao.w);
            }
            float4 ai = make_float4(0.f, 0.f, 0.f, 0.f);
            p0 = g_ptr_i[n]; p1 = g_ptr_i[n + 1];
            for (int p = p0; p < p1; ++p) {
                float4 v = bi[g_col_i[p]];
                ai.x += v.x; ai.y += v.y; ai.z += v.z; ai.w += v.w;
            }
            float wi = g_invdi[n];
            float4 ro, ri;
            ro.x = fmaf(2.f, ao.x, -sub.x); ro.y = fmaf(2.f, ao.y, -sub.y);
            ro.z = fmaf(2.f, ao.z, -sub.z); ro.w = fmaf(2.f, ao.w, -sub.w);
            ri.x = fmaf(2.f * wi, ai.x, -sub.x); ri.y = fmaf(2.f * wi, ai.y, -sub.y);
            ri.z = fmaf(2.f * wi, ai.z, -sub.z); ri.w = fmaf(2.f * wi, ai.w, -sub.w);
            bf[n] = ro; t0[n] = ri;
            *(float4*)(Tb + (size_t)n * KD + (size_t)k * 64) = ro;
            *(float4*)(Tb + (size_t)n * KD + (size_t)(4 + k) * 64) = ri;
        }
        __syncthreads();
        float4* nt0 = bo; float4* no = bf; float4* ni = t0; float4* nf = bi;
        t0 = nt0; bo = no; bi = ni; bf = nf;
    }
}

// ---------------- tf32 mma GEMM + fused bias/act/LayerNorm epilogue ----------------
__device__ __forceinline__ float to_tf32(float x) {
    uint32_t u; asm("cvt.rna.tf32.f32 %0, %1;" : "=r"(u) : "f"(x));
    return __uint_as_float(u);
}
__device__ __forceinline__ void mma_tf32(float* c, const uint32_t* a, const uint32_t* b) {
    asm volatile("mma.sync.aligned.m16n8k8.row.col.f32.tf32.tf32.f32 "
                 "{%0,%1,%2,%3}, {%4,%5,%6,%7}, {%8,%9}, {%0,%1,%2,%3};\n"
                 : "+f"(c[0]), "+f"(c[1]), "+f"(c[2]), "+f"(c[3])
                 : "r"(a[0]), "r"(a[1]), "r"(a[2]), "r"(a[3]), "r"(b[0]), "r"(b[1]));
}
__device__ __forceinline__ float sigf(float x) { return 1.0f / (1.0f + expf(-x)); }

#define ASTR 36
#define BSTR 136
#define ASZ (128 * ASTR)
#define BSZ (32 * BSTR)

__global__ void __launch_bounds__(256, 1) k_gemm(const float* __restrict__ A,
                                                 const float* __restrict__ B,
                                                 const float* __restrict__ lng,
                                                 const float* __restrict__ lnb) {
    extern __shared__ float sm[];
    float* As = sm;             // 2 * 128 * 36
    float* Bs = sm + 2 * ASZ;   // 2 * 32 * 136

    const int tid = threadIdx.x;
    const int mbase = blockIdx.x * 128;
    const int ar = tid >> 1, ah = tid & 1;
    const int br = tid >> 3, bc = (tid & 7) * 16;
    const float* Ag = A + (size_t)mbase * KD;

    float acc[2][8][4];
#pragma unroll
    for (int a = 0; a < 2; ++a)
#pragma unroll
        for (int b = 0; b < 8; ++b)
#pragma unroll
            for (int q = 0; q < 4; ++q) acc[a][b][q] = 0.f;

    float4 la[4], lb[4];
    {
        const float4* p = (const float4*)(Ag + (size_t)ar * KD + ah * 16);
#pragma unroll
        for (int j = 0; j < 4; ++j) la[j] = p[j];
        const float4* q = (const float4*)(B + (size_t)br * 128 + bc);
#pragma unroll
        for (int j = 0; j < 4; ++j) lb[j] = q[j];
        float* d = As + ar * ASTR + ah * 16;
#pragma unroll
        for (int j = 0; j < 4; ++j) {
            d[4 * j + 0] = to_tf32(la[j].x); d[4 * j + 1] = to_tf32(la[j].y);
            d[4 * j + 2] = to_tf32(la[j].z); d[4 * j + 3] = to_tf32(la[j].w);
        }
        float* e = Bs + br * BSTR + bc;
#pragma unroll
        for (int j = 0; j < 4; ++j) {
            e[4 * j + 0] = to_tf32(lb[j].x); e[4 * j + 1] = to_tf32(lb[j].y);
            e[4 * j + 2] = to_tf32(lb[j].z); e[4 * j + 3] = to_tf32(lb[j].w);
        }
    }
    __syncthreads();

    const int lane = tid & 31, wid = tid >> 5;
    const int wm = wid & 3, wn = wid >> 2;
    const int g = lane >> 2, tg = lane & 3;

    for (int st = 0; st < NSTAGE; ++st) {
        int buf = st & 1;
        if (st + 1 < NSTAGE) {
            int k0 = (st + 1) * 32;
            const float4* p = (const float4*)(Ag + (size_t)ar * KD + k0 + ah * 16);
#pragma unroll
            for (int j = 0; j < 4; ++j) la[j] = p[j];
            const float4* q = (const float4*)(B + (size_t)(k0 + br) * 128 + bc);
#pragma unroll
            for (int j = 0; j < 4; ++j) lb[j] = q[j];
        }
        const float* Ab = As + buf * ASZ;
        const float* Bb = Bs + buf * BSZ;
#pragma unroll
        for (int kb = 0; kb < 4; ++kb) {
            uint32_t bf[8][2];
#pragma unroll
            for (int nt = 0; nt < 8; ++nt) {
                int n = wn * 64 + nt * 8 + g;
                bf[nt][0] = __float_as_uint(Bb[(kb * 8 + tg) * BSTR + n]);
                bf[nt][1] = __float_as_uint(Bb[(kb * 8 + tg + 4) * BSTR + n]);
            }
#pragma unroll
            for (int mt = 0; mt < 2; ++mt) {
                int R = wm * 32 + mt * 16 + g;
                uint32_t af[4];
                af[0] = __float_as_uint(Ab[R * ASTR + kb * 8 + tg]);
                af[1] = __float_as_uint(Ab[(R + 8) * ASTR + kb * 8 + tg]);
                af[2] = __float_as_uint(Ab[R * ASTR + kb * 8 + tg + 4]);
                af[3] = __float_as_uint(Ab[(R + 8) * ASTR + kb * 8 + tg + 4]);
#pragma unroll
                for (int nt = 0; nt < 8; ++nt) mma_tf32(acc[mt][nt], af, bf[nt]);
            }
        }
        __syncthreads();
        if (st + 1 < NSTAGE) {
            float* d = As + (1 - buf) * ASZ + ar * ASTR + ah * 16;
#pragma unroll
            for (int j = 0; j < 4; ++j) {
                d[4 * j + 0] = to_tf32(la[j].x); d[4 * j + 1] = to_tf32(la[j].y);
                d[4 * j + 2] = to_tf32(la[j].z); d[4 * j + 3] = to_tf32(la[j].w);
            }
            float* e = Bs + (1 - buf) * BSZ + br * BSTR + bc;
#pragma unroll
            for (int j = 0; j < 4; ++j) {
                e[4 * j + 0] = to_tf32(lb[j].x); e[4 * j + 1] = to_tf32(lb[j].y);
                e[4 * j + 2] = to_tf32(lb[j].z); e[4 * j + 3] = to_tf32(lb[j].w);
            }
            __syncthreads();
        }
    }

    // ---- fused epilogue: stage C tile -> bias -> gate -> relu -> LayerNorm -> g_hn ----
    __syncthreads();
    float* S = sm;  // 128 x 136 staging
#pragma unroll
    for (int mt = 0; mt < 2; ++mt)
#pragma unroll
        for (int nt = 0; nt < 8; ++nt) {
            int Rl = wm * 32 + mt * 16 + g;
            int Cl = wn * 64 + nt * 8 + 2 * tg;
            S[Rl * 136 + Cl]         = acc[mt][nt][0];
            S[Rl * 136 + Cl + 1]     = acc[mt][nt][1];
            S[(Rl + 8) * 136 + Cl]   = acc[mt][nt][2];
            S[(Rl + 8) * 136 + Cl + 1] = acc[mt][nt][3];
        }
    __syncthreads();
    float bz0 = g_bias[lane], bz1 = g_bias[lane + 32];
    float bh0 = g_bias[64 + lane], bh1 = g_bias[96 + lane];
    float gg0 = lng[lane], gg1 = lng[lane + 32];
    float lb0 = lnb[lane], lb1 = lnb[lane + 32];
#pragma unroll 4
    for (int rr = 0; rr < 16; ++rr) {
        int rl = wid * 16 + rr;
        const float* Sr = S + rl * 136;
        float za = Sr[lane] + bz0;
        float zb = Sr[lane + 32] + bz1;
        float ha = Sr[64 + lane] + bh0;
        float hb = Sr[96 + lane] + bh1;
        float va = fmaxf(0.f, (1.f - sigf(za)) * tanhf(ha));
        float vb = fmaxf(0.f, (1.f - sigf(zb)) * tanhf(hb));
        float s = va + vb, sq = va * va + vb * vb;
#pragma unroll
        for (int off = 16; off > 0; off >>= 1) {
            s  += __shfl_xor_sync(0xffffffffu, s, off);
            sq += __shfl_xor_sync(0xffffffffu, sq, off);
        }
        float mean = s * (1.0f / 64.0f);
        float var = sq * (1.0f / 64.0f) - mean * mean;
        float rstd = rsqrtf(var + 1e-5f);
        float* d = g_hn + (size_t)(mbase + rl) * 64;
        d[lane]      = (va - mean) * rstd * gg0 + lb0;
        d[lane + 32] = (vb - mean) * rstd * gg1 + lb1;
    }
}

// ---------------- final linear (two-stage, no float atomics) ----------------
#define CHUNK 16000
__global__ void k_fin1(const float* __restrict__ lw) {
    int bg = blockIdx.x / 48;      // batch group of 4
    int ch = blockIdx.x % 48;
    int tid = threadIdx.x, lane = tid & 31, wid = tid >> 5;
    float a[4][10];
#pragma unroll
    for (int b = 0; b < 4; ++b)
#pragma unroll
        for (int c = 0; c < 10; ++c) a[b][c] = 0.f;
    int i0 = ch * CHUNK, i1 = i0 + CHUNK;
    for (int i = i0 + tid; i < i1; i += 256) {
        float hv[4];
#pragma unroll
        for (int b = 0; b < 4; ++b) hv[b] = g_hn[(size_t)(bg * 4 + b) * 768000 + i];
#pragma unroll
        for (int c = 0; c < 10; ++c) {
            float w = lw[(size_t)c * 768000 + i];
#pragma unroll
            for (int b = 0; b < 4; ++b) a[b][c] = fmaf(hv[b], w, a[b][c]);
        }
    }
    __shared__ float sred[8][40];
    float* av = &a[0][0];
#pragma unroll
    for (int q = 0; q < 40; ++q) {
        float x = av[q];
#pragma unroll
        for (int off = 16; off > 0; off >>= 1) x += __shfl_xor_sync(0xffffffffu, x, off);
        av[q] = x;
    }
    if (lane == 0)
#pragma unroll
        for (int q = 0; q < 40; ++q) sred[wid][q] = av[q];
    __syncthreads();
    if (tid < 40) {
        float ssum = 0.f;
#pragma unroll
        for (int w = 0; w < 8; ++w) ssum += sred[w][tid];
        g_part[blockIdx.x * 40 + tid] = ssum;
    }
}

__global__ void k_fin2(const float* __restrict__ lb, float* __restrict__ out) {
    int t = threadIdx.x;
    if (t < 160) {
        int b = t / 10, c = t % 10;
        int bg = b >> 2, bb = b & 3;
        float s = lb[c];
        for (int ch = 0; ch < 48; ++ch) s += g_part[(bg * 48 + ch) * 40 + bb * 10 + c];
        out[t] = s;
    }
}

// ---------------- launch ----------------
extern "C" void kernel_launch(void* const* d_in, const int* in_sizes, int n_in,
                              void* d_out, int out_size) {
    const float* x   = (const float*)d_in[0];
    const int*   ei  = (const int*)d_in[1];
    const float* Wz  = (const float*)d_in[2];
    const float* bz  = (const float*)d_in[3];
    const float* Wh  = (const float*)d_in[6];
    const float* bh  = (const float*)d_in[7];
    const float* lng = (const float*)d_in[8];
    const float* lnb = (const float*)d_in[9];
    const float* lw  = (const float*)d_in[10];
    const float* lb  = (const float*)d_in[11];
    int E = in_sizes[1] / 2;

    const int smem_gemm = (2 * ASZ + 2 * BSZ) * 4;   // 71680 B (>= 128*136*4 epilogue staging)
    cudaFuncSetAttribute(k_gemm, cudaFuncAttributeMaxDynamicSharedMemorySize, smem_gemm);
    const int smem_chain = 4 * 1024 * 16;            // 65536 B
    cudaFuncSetAttribute(k_chain, cudaFuncAttributeMaxDynamicSharedMemorySize, smem_chain);

    float* dT;  cudaGetSymbolAddress((void**)&dT, g_T);
    float* dW;  cudaGetSymbolAddress((void**)&dW, g_W);

    k_setup<<<1, 1024>>>(ei, E);
    k_scatter<<<(E + 255) / 256, 256>>>(ei, E);
    k_prepw<<<KD, 128>>>(Wz, Wh, bz, bh);
    k_chain<<<SS * 16, 256, smem_chain>>>(x);
    k_gemm<<<1500, 256, smem_gemm>>>(dT, dW, lng, lnb);
    k_fin1<<<192, 256>>>(lw);
    k_fin2<<<1, 192>>>(lb, (float*)d_out);
}